// round 2
// baseline (speedup 1.0000x reference)
#include <cuda_runtime.h>
#include <cstdint>

// Problem constants
#define NB   32
#define NAC  5
#define NC   20
#define NH   76
#define NW   76
#define MAXT 50
#define CELLS_PER_IMG (NAC * NH * NW)   // 28880
#define PLANE (NH * NW)                 // 5776
#define BLK   256
#define GX    113                        // ceil(28880/256)
#define NBLOCKS (GX * NB)                // 3616

#define SIL_NUM 3.0f   // iou > 0.6  <=>  8*carea > 3*(pa+ga)
#define SIL_DEN 8.0f

// -------- device scratch (no allocations allowed) --------
__device__ float g_partial[NBLOCKS];
__device__ unsigned int g_counter = 0;

__device__ __forceinline__ float sigf(float v) {
    return 1.0f / (1.0f + __expf(-v));
}

// ---------------- Single fused kernel ----------------
__global__ __launch_bounds__(BLK) void k_fused(const float* __restrict__ out,
                                               const float* __restrict__ tgt,
                                               const float* __restrict__ anch,
                                               float* __restrict__ outv) {
    const int b   = blockIdx.y;
    const int tid = threadIdx.x;
    const int cellInImg = blockIdx.x * BLK + tid;

    __shared__ float s_aw[NAC], s_ah[NAC];
    __shared__ int   s_vflag[MAXT];
    __shared__ int   s_cnt;
    __shared__ float s_f[MAXT][9];   // gx,gy,gw,gh, tx,ty,tw,th, tconf (compacted)
    __shared__ int   s_cell[MAXT];
    __shared__ int   s_cls[MAXT];
    __shared__ float red[BLK];
    __shared__ bool  isLast;

    if (tid < NAC) { s_aw[tid] = anch[2 * tid]; s_ah[tid] = anch[2 * tid + 1]; }
    __syncthreads();

    // ---- per-target prep (threads 0..MAXT-1), redundant per block ----
    bool  valid = false;
    float gx = 0, gy = 0, gw = 0, gh = 0, tx = 0, ty = 0, tw = 0, th = 0, tconf = 0;
    int   cell = -1, cls = 0;

    if (tid < MAXT) {
        const float* tp = tgt + (b * MAXT + tid) * 5;
        float f0 = tp[0], f1 = tp[1], f2 = tp[2], f3 = tp[3], f4 = tp[4];
        valid = (f1 != 0.0f);
        s_vflag[tid] = valid ? 1 : 0;
        if (valid) {
            gx = f1 * (float)NW; gy = f2 * (float)NH;
            gw = f3 * (float)NW; gh = f4 * (float)NH;
            cls = (int)f0;
            float best = -1.0f; int bn = 0;
            float garea = gw * gh;
            #pragma unroll
            for (int a = 0; a < NAC; a++) {
                float cw = fminf(gw, s_aw[a]);
                float ch = fminf(gh, s_ah[a]);
                float ca = cw * ch;
                float iou = ca / (garea + s_aw[a] * s_ah[a] - ca);
                if (iou > best) { best = iou; bn = a; }
            }
            int gi = min(max((int)gx, 0), NW - 1);
            int gj = min(max((int)gy, 0), NH - 1);
            cell = (bn * NH + gj) * NW + gi;
            tx = gx - (float)gi;
            ty = gy - (float)gj;
            tw = __logf(gw / s_aw[bn]);
            th = __logf(gh / s_ah[bn]);
            const float* p = out + (size_t)(b * (NAC * (5 + NC)) + bn * (5 + NC)) * PLANE
                                 + gj * NW + gi;
            float px = sigf(p[0]) + (float)gi;
            float py = sigf(p[PLANE]) + (float)gj;
            float pw = __expf(p[2 * PLANE]) * s_aw[bn];
            float ph = __expf(p[3 * PLANE]) * s_ah[bn];
            float uw = fmaxf(gx + 0.5f * gw, px + 0.5f * pw) - fminf(gx - 0.5f * gw, px - 0.5f * pw);
            float uh = fmaxf(gy + 0.5f * gh, py + 0.5f * ph) - fminf(gy - 0.5f * gh, py - 0.5f * ph);
            float cw = gw + pw - uw;
            float ch = gh + ph - uh;
            float ca = (cw <= 0.0f || ch <= 0.0f) ? 0.0f : cw * ch;
            tconf = ca / (garea + pw * ph - ca);
        }
    }
    __syncthreads();

    if (tid < MAXT && valid) {
        int slot = 0;
        for (int k = 0; k < tid; k++) slot += s_vflag[k];
        float* dst = s_f[slot];
        dst[0] = gx; dst[1] = gy; dst[2] = gw; dst[3] = gh;
        dst[4] = tx; dst[5] = ty; dst[6] = tw; dst[7] = th; dst[8] = tconf;
        s_cell[slot] = cell;
        s_cls[slot]  = cls;
    }
    if (tid == 0) {
        int c = 0;
        #pragma unroll
        for (int k = 0; k < MAXT; k++) c += s_vflag[k];
        s_cnt = c;
    }
    __syncthreads();

    const int cnt = s_cnt;

    // ---- per-cell loss ----
    float loss = 0.0f;
    if (cellInImg < CELLS_PER_IMG) {
        int a   = cellInImg / PLANE;
        int rem = cellInImg - a * PLANE;
        int j   = rem / NW;
        int i   = rem - j * NW;

        const float* p = out + (size_t)(b * (NAC * (5 + NC)) + a * (5 + NC)) * PLANE + rem;
        float o0 = p[0];
        float o1 = p[PLANE];
        float o2 = p[2 * PLANE];
        float o3 = p[3 * PLANE];
        float o4 = p[4 * PLANE];

        float x    = sigf(o0);
        float y    = sigf(o1);
        float conf = sigf(o4);
        float px = x + (float)i;
        float py = y + (float)j;
        float pw = __expf(o2) * s_aw[a];
        float ph = __expf(o3) * s_ah[a];
        float parea = pw * ph;
        float phx = px + 0.5f * pw, plx = px - 0.5f * pw;
        float phy = py + 0.5f * ph, ply = py - 0.5f * ph;

        float noobj = 1.0f;      // NOOBJ_SCALE
        int   tm = -1;
        for (int t = 0; t < cnt; t++) {
            if (s_cell[t] == cellInImg) tm = t;
            float gxx = s_f[t][0], gyy = s_f[t][1], gww = s_f[t][2], ghh = s_f[t][3];
            float uw = fmaxf(phx, gxx + 0.5f * gww) - fminf(plx, gxx - 0.5f * gww);
            float uh = fmaxf(phy, gyy + 0.5f * ghh) - fminf(ply, gyy - 0.5f * ghh);
            float cw = pw + gww - uw;
            float ch = ph + ghh - uh;
            if (cw > 0.0f && ch > 0.0f) {
                float ca = cw * ch;
                if (SIL_DEN * ca > SIL_NUM * (parea + gww * ghh)) noobj = 0.0f;
            }
        }

        if (tm >= 0) {
            float ttx = s_f[tm][4], tty = s_f[tm][5], ttw = s_f[tm][6], tth = s_f[tm][7];
            float tcf = s_f[tm][8];
            int   c0  = s_cls[tm];
            float dx = x  - ttx, dy = y  - tty, dw = o2 - ttw, dh = o3 - tth;
            loss += 0.5f * (dx * dx + dy * dy + dw * dw + dh * dh);
            float dc = conf - tcf;
            loss += 0.5f * 5.0f * dc * dc;   // OBJ_SCALE
            float lg[NC];
            float mx = -1e30f;
            #pragma unroll
            for (int c = 0; c < NC; c++) {
                lg[c] = p[(5 + c) * PLANE];
                mx = fmaxf(mx, lg[c]);
            }
            float se = 0.0f;
            #pragma unroll
            for (int c = 0; c < NC; c++) se += __expf(lg[c] - mx);
            loss += (__logf(se) + mx) - lg[c0];
        } else {
            loss += 0.5f * noobj * conf * conf;
        }
    }

    // ---- block reduction ----
    red[tid] = loss;
    __syncthreads();
    #pragma unroll
    for (int s = BLK / 2; s > 32; s >>= 1) {
        if (tid < s) red[tid] += red[tid + s];
        __syncthreads();
    }
    if (tid < 32) {
        float v = red[tid] + red[tid + 32];
        #pragma unroll
        for (int off = 16; off > 0; off >>= 1)
            v += __shfl_down_sync(0xFFFFFFFFu, v, off);
        if (tid == 0) g_partial[blockIdx.y * gridDim.x + blockIdx.x] = v;
    }

    // ---- last-block final reduction ----
    if (tid == 0) {
        __threadfence();
        unsigned int v = atomicAdd(&g_counter, 1u);
        isLast = (v == (unsigned int)(NBLOCKS - 1));
    }
    __syncthreads();
    if (isLast) {
        double acc = 0.0;
        for (int i2 = tid; i2 < NBLOCKS; i2 += BLK) acc += (double)g_partial[i2];
        // reuse red[] as double via two-pass: store to shared as double pairs
        __shared__ double dred[BLK];
        dred[tid] = acc;
        __syncthreads();
        #pragma unroll
        for (int s = BLK / 2; s > 0; s >>= 1) {
            if (tid < s) dred[tid] += dred[tid + s];
            __syncthreads();
        }
        if (tid == 0) {
            outv[0] = (float)(dred[0] / (double)NB);
            g_counter = 0;   // reset for next graph replay
        }
    }
}

extern "C" void kernel_launch(void* const* d_in, const int* in_sizes, int n_in,
                              void* d_out, int out_size) {
    const float* out  = (const float*)d_in[0];
    const float* tgt  = (const float*)d_in[1];
    const float* anch = (const float*)d_in[2];
    float* o = (float*)d_out;

    dim3 g(GX, NB);
    k_fused<<<g, BLK>>>(out, tgt, anch, o);
}

// round 3
// speedup vs baseline: 1.8052x; 1.8052x over previous
#include <cuda_runtime.h>
#include <cstdint>

// Problem constants
#define NB    32
#define NAC   5
#define NC    20
#define NH    76
#define NW    76
#define MAXT  50
#define PLANE (NH * NW)                 // 5776
#define QPA   (PLANE / 4)               // 1444 quads per anchor plane
#define QPI   (NAC * QPA)               // 7220 quads per image
#define BLK   256
#define GX    29                        // ceil(7220/256)
#define NBLOCKS (GX * NB)               // 928

// -------- device scratch (no allocations allowed) --------
__device__ float g_partial[NBLOCKS];
__device__ unsigned int g_counter = 0;

__device__ __forceinline__ float sigf(float v) {
    return __fdividef(1.0f, 1.0f + __expf(-v));
}

__global__ __launch_bounds__(BLK) void k_fused(const float* __restrict__ out,
                                               const float* __restrict__ tgt,
                                               const float* __restrict__ anch,
                                               float* __restrict__ outv) {
    const int b   = blockIdx.y;
    const int tid = threadIdx.x;
    const int q   = blockIdx.x * BLK + tid;

    __shared__ float4 s_box[MAXT];   // gx1, gy1, gx2, gy2
    __shared__ float  s_thr[MAXT];   // 0.375 * garea
    __shared__ int    s_cnt;
    __shared__ float  red[BLK];
    __shared__ bool   isLast;

    if (tid == 0) s_cnt = 0;
    __syncthreads();

    // ---- per-target box prep (cheap, all blocks) ----
    float gx = 0, gy = 0, gw = 0, gh = 0;
    int   cls = 0;
    bool  valid = false;
    if (tid < MAXT) {
        const float* tp = tgt + (b * MAXT + tid) * 5;
        float f0 = tp[0], f1 = tp[1], f2 = tp[2], f3 = tp[3], f4 = tp[4];
        valid = (f1 != 0.0f);
        if (valid) {
            gx = f1 * (float)NW; gy = f2 * (float)NH;
            gw = f3 * (float)NW; gh = f4 * (float)NH;
            cls = (int)f0;
            int slot = atomicAdd(&s_cnt, 1);
            s_box[slot] = make_float4(gx - 0.5f * gw, gy - 0.5f * gh,
                                      gx + 0.5f * gw, gy + 0.5f * gh);
            s_thr[slot] = 0.375f * gw * gh;
        }
    }
    __syncthreads();
    const int cnt = s_cnt;

    float loss = 0.0f;

    // ---- main per-cell noobj loss (4 cells per thread) ----
    if (q < QPI) {
        int a   = q / QPA;
        int r4  = q - a * QPA;
        int rem = r4 * 4;
        int j   = rem / NW;
        int i0  = rem - j * NW;

        const float* p = out + ((size_t)b * (NAC * 25) + a * 25) * PLANE + rem;
        float4 v0 = *(const float4*)(p);
        float4 v1 = *(const float4*)(p + PLANE);
        float4 v2 = *(const float4*)(p + 2 * PLANE);
        float4 v3 = *(const float4*)(p + 3 * PLANE);
        float4 v4 = *(const float4*)(p + 4 * PLANE);
        float aw = __ldg(&anch[2 * a]);
        float ah = __ldg(&anch[2 * a + 1]);

        float o0[4] = {v0.x, v0.y, v0.z, v0.w};
        float o1[4] = {v1.x, v1.y, v1.z, v1.w};
        float o2[4] = {v2.x, v2.y, v2.z, v2.w};
        float o3[4] = {v3.x, v3.y, v3.z, v3.w};
        float o4[4] = {v4.x, v4.y, v4.z, v4.w};

        float plx[4], phx[4], ply[4], phy[4], thrP[4], cf[4], keep[4];
        #pragma unroll
        for (int c = 0; c < 4; c++) {
            float x = sigf(o0[c]);
            float y = sigf(o1[c]);
            cf[c]   = sigf(o4[c]);
            float px = x + (float)(i0 + c);
            float py = y + (float)j;
            float pw = __expf(o2[c]) * aw;
            float ph = __expf(o3[c]) * ah;
            plx[c] = px - 0.5f * pw; phx[c] = px + 0.5f * pw;
            ply[c] = py - 0.5f * ph; phy[c] = py + 0.5f * ph;
            thrP[c] = 0.375f * pw * ph;
            keep[c] = 1.0f;
        }

        for (int t = 0; t < cnt; t++) {
            float4 gb  = s_box[t];
            float  th3 = s_thr[t];
            #pragma unroll
            for (int c = 0; c < 4; c++) {
                float iw = fminf(phx[c], gb.z) - fmaxf(plx[c], gb.x);
                float ih = fminf(phy[c], gb.w) - fmaxf(ply[c], gb.y);
                iw = fmaxf(iw, 0.0f);
                ih = fmaxf(ih, 0.0f);
                if (iw * ih > thrP[c] + th3) keep[c] = 0.0f;
            }
        }
        #pragma unroll
        for (int c = 0; c < 4; c++)
            loss += 0.5f * keep[c] * cf[c] * cf[c];
    }

    // ---- matched-cell loss: one block per image handles its 12 GTs ----
    if (blockIdx.x == 0 && valid) {
        // best anchor
        float ga = gw * gh;
        float best = -1.0f; int bn = 0;
        #pragma unroll
        for (int an = 0; an < NAC; an++) {
            float aww = anch[2 * an], ahh = anch[2 * an + 1];
            float ca  = fminf(gw, aww) * fminf(gh, ahh);
            float iou = ca / (ga + aww * ahh - ca);
            if (iou > best) { best = iou; bn = an; }
        }
        float aw = anch[2 * bn], ah = anch[2 * bn + 1];
        int gi = min(max((int)gx, 0), NW - 1);
        int gj = min(max((int)gy, 0), NH - 1);
        float txv = gx - (float)gi;
        float tyv = gy - (float)gj;
        float twv = __logf(gw / aw);
        float thv = __logf(gh / ah);

        const float* p = out + ((size_t)b * (NAC * 25) + bn * 25) * PLANE + gj * NW + gi;
        float o0 = p[0];
        float o1 = p[PLANE];
        float o2 = p[2 * PLANE];
        float o3 = p[3 * PLANE];
        float o4 = p[4 * PLANE];
        float x = sigf(o0), y = sigf(o1), conf = sigf(o4);
        float px = x + (float)gi;
        float py = y + (float)gj;
        float pw = __expf(o2) * aw;
        float ph = __expf(o3) * ah;

        // tconf = iou(gt, pred)
        {
            float iw = fminf(px + 0.5f * pw, gx + 0.5f * gw) - fmaxf(px - 0.5f * pw, gx - 0.5f * gw);
            float ih = fminf(py + 0.5f * ph, gy + 0.5f * gh) - fmaxf(py - 0.5f * ph, gy - 0.5f * gh);
            float ca = (iw <= 0.0f || ih <= 0.0f) ? 0.0f : iw * ih;
            float tconf = ca / (pw * ph + ga - ca);

            // silence result for this cell — must mirror main-loop computation
            float plx = px - 0.5f * pw, phx = px + 0.5f * pw;
            float ply = py - 0.5f * ph, phy = py + 0.5f * ph;
            float thrP = 0.375f * pw * ph;
            float keep = 1.0f;
            for (int t = 0; t < cnt; t++) {
                float4 gb  = s_box[t];
                float  th3 = s_thr[t];
                float iw2 = fminf(phx, gb.z) - fmaxf(plx, gb.x);
                float ih2 = fminf(phy, gb.w) - fmaxf(ply, gb.y);
                iw2 = fmaxf(iw2, 0.0f);
                ih2 = fmaxf(ih2, 0.0f);
                if (iw2 * ih2 > thrP + th3) keep = 0.0f;
            }

            // cross-entropy over 20 classes
            float lg[NC];
            float mx = -1e30f;
            #pragma unroll
            for (int c = 0; c < NC; c++) {
                lg[c] = p[(5 + c) * PLANE];
                mx = fmaxf(mx, lg[c]);
            }
            float se = 0.0f;
            #pragma unroll
            for (int c = 0; c < NC; c++) se += __expf(lg[c] - mx);
            float ce = (__logf(se) + mx) - lg[cls];

            float dx = x  - txv, dy = y  - tyv;
            float dw = o2 - twv, dh = o3 - thv;
            float dc = conf - tconf;
            loss += 0.5f * (dx * dx + dy * dy + dw * dw + dh * dh)
                  + 2.5f * dc * dc
                  + ce
                  - 0.5f * keep * conf * conf;   // cancel main-loop noobj term
        }
    }

    // ---- block reduction ----
    red[tid] = loss;
    __syncthreads();
    #pragma unroll
    for (int s = BLK / 2; s > 32; s >>= 1) {
        if (tid < s) red[tid] += red[tid + s];
        __syncthreads();
    }
    if (tid < 32) {
        float v = red[tid] + red[tid + 32];
        #pragma unroll
        for (int off = 16; off > 0; off >>= 1)
            v += __shfl_down_sync(0xFFFFFFFFu, v, off);
        if (tid == 0) g_partial[blockIdx.y * gridDim.x + blockIdx.x] = v;
    }

    // ---- last-block final reduction ----
    if (tid == 0) {
        __threadfence();
        unsigned int v = atomicAdd(&g_counter, 1u);
        isLast = (v == (unsigned int)(NBLOCKS - 1));
    }
    __syncthreads();
    if (isLast) {
        double acc = 0.0;
        for (int i2 = tid; i2 < NBLOCKS; i2 += BLK) acc += (double)g_partial[i2];
        __shared__ double dred[BLK];
        dred[tid] = acc;
        __syncthreads();
        #pragma unroll
        for (int s = BLK / 2; s > 0; s >>= 1) {
            if (tid < s) dred[tid] += dred[tid + s];
            __syncthreads();
        }
        if (tid == 0) {
            outv[0] = (float)(dred[0] / (double)NB);
            g_counter = 0;   // reset for next graph replay
        }
    }
}

extern "C" void kernel_launch(void* const* d_in, const int* in_sizes, int n_in,
                              void* d_out, int out_size) {
    const float* out  = (const float*)d_in[0];
    const float* tgt  = (const float*)d_in[1];
    const float* anch = (const float*)d_in[2];
    float* o = (float*)d_out;

    dim3 g(GX, NB);
    k_fused<<<g, BLK>>>(out, tgt, anch, o);
}